// round 1
// baseline (speedup 1.0000x reference)
#include <cuda_runtime.h>
#include <math.h>

#define HH 40
#define WW 40
#define CIN 2048
#define NPIX 1600
#define CMID 256
#define NA 5
#define NBOX 8000
#define NWORD 125
#define MAXDET 300

// ---------------- device scratch (static, no allocation) ----------------
__device__ float g_partial[9 * NPIX * CMID];   // per-tap GEMM partials (14.7 MB)
__device__ float g_x[NPIX * CMID];             // conv output after bias+relu
__device__ float g_scores[NBOX];
__device__ float g_boxes[NBOX * 4];
__device__ float g_boxsorted[NBOX * 4];
__device__ float g_rois[MAXDET * 4];

// ---------------- K1: per-tap 64x64x16 tiled SGEMM ----------------
// grid (25 m-tiles, 4 n-tiles, 9 taps), 256 threads, 4x4 per-thread tile,
// double-buffered shared memory. Writes fp32 partials (deterministic).
__global__ __launch_bounds__(256) void conv_tap_kernel(
    const float* __restrict__ feat, const float* __restrict__ wconv) {
  __shared__ __align__(16) float As[2][16][68];
  __shared__ __align__(16) float Bs[2][16][64];
  const int mt  = blockIdx.x;
  const int nt  = blockIdx.y;
  const int tap = blockIdx.z;
  const int ky = tap / 3, kx = tap % 3;
  const float* wt = wconv + (size_t)tap * CIN * CMID;  // w[ky][kx][k][n]
  const int tid = threadIdx.x;
  const int tn = (tid & 15) * 4;
  const int tm = (tid >> 4) * 4;
  // A staging: thread loads float4 along k
  const int m_a = tid >> 2;            // 0..63
  const int k_a = (tid & 3) * 4;       // 0,4,8,12
  const int m = mt * 64 + m_a;
  const int y = m / WW, x = m % WW;
  const int yy = y + ky - 1, xx = x + kx - 1;
  const bool valid = (yy >= 0 && yy < HH && xx >= 0 && xx < WW);
  const float* arow = feat + (size_t)(valid ? (yy * WW + xx) : 0) * CIN;
  // B staging: thread loads float4 along n
  const int k_b = tid >> 4;            // 0..15
  const int n_b = (tid & 15) * 4;
  const int n0 = nt * 64;

  float acc[4][4];
#pragma unroll
  for (int i = 0; i < 4; i++)
#pragma unroll
    for (int j = 0; j < 4; j++) acc[i][j] = 0.f;

  float4 ra = valid ? *(const float4*)(arow + k_a) : make_float4(0.f, 0.f, 0.f, 0.f);
  float4 rb = *(const float4*)(wt + (size_t)k_b * CMID + n0 + n_b);
  As[0][k_a + 0][m_a] = ra.x;
  As[0][k_a + 1][m_a] = ra.y;
  As[0][k_a + 2][m_a] = ra.z;
  As[0][k_a + 3][m_a] = ra.w;
  *(float4*)&Bs[0][k_b][n_b] = rb;
  __syncthreads();

  int buf = 0;
#pragma unroll 1
  for (int k0 = 16; k0 < CIN; k0 += 16) {
    float4 na = valid ? *(const float4*)(arow + k0 + k_a) : make_float4(0.f, 0.f, 0.f, 0.f);
    float4 nbv = *(const float4*)(wt + (size_t)(k0 + k_b) * CMID + n0 + n_b);
#pragma unroll
    for (int k = 0; k < 16; k++) {
      float4 av = *(const float4*)&As[buf][k][tm];
      float4 bv = *(const float4*)&Bs[buf][k][tn];
      float af[4] = {av.x, av.y, av.z, av.w};
      float bf[4] = {bv.x, bv.y, bv.z, bv.w};
#pragma unroll
      for (int i = 0; i < 4; i++)
#pragma unroll
        for (int j = 0; j < 4; j++) acc[i][j] = fmaf(af[i], bf[j], acc[i][j]);
    }
    const int ob = buf ^ 1;
    As[ob][k_a + 0][m_a] = na.x;
    As[ob][k_a + 1][m_a] = na.y;
    As[ob][k_a + 2][m_a] = na.z;
    As[ob][k_a + 3][m_a] = na.w;
    *(float4*)&Bs[ob][k_b][n_b] = nbv;
    __syncthreads();
    buf = ob;
  }
#pragma unroll
  for (int k = 0; k < 16; k++) {
    float4 av = *(const float4*)&As[buf][k][tm];
    float4 bv = *(const float4*)&Bs[buf][k][tn];
    float af[4] = {av.x, av.y, av.z, av.w};
    float bf[4] = {bv.x, bv.y, bv.z, bv.w};
#pragma unroll
    for (int i = 0; i < 4; i++)
#pragma unroll
      for (int j = 0; j < 4; j++) acc[i][j] = fmaf(af[i], bf[j], acc[i][j]);
  }

  float* cp = g_partial + (size_t)tap * (NPIX * CMID);
#pragma unroll
  for (int i = 0; i < 4; i++) {
    float4 v = make_float4(acc[i][0], acc[i][1], acc[i][2], acc[i][3]);
    *(float4*)&cp[(size_t)(mt * 64 + tm + i) * CMID + n0 + tn] = v;
  }
}

// ---------------- K2: reduce 9 partials + bias + relu ----------------
__global__ __launch_bounds__(256) void reduce_bias_relu(const float* __restrict__ bias) {
  int i = blockIdx.x * 256 + threadIdx.x;  // 409600 elements
  float s = bias[i & 255];
#pragma unroll
  for (int t = 0; t < 9; t++) s += g_partial[(size_t)t * (NPIX * CMID) + i];
  g_x[i] = fmaxf(s, 0.f);
}

// ---------------- K3: 1x1 heads + score + anchor decode ----------------
__global__ __launch_bounds__(32) void head_conv_kernel(
    const float* __restrict__ cls_w, const float* __restrict__ cls_b,
    const float* __restrict__ reg_w, const float* __restrict__ reg_b) {
  const int p = blockIdx.x;      // pixel 0..1599
  const int lane = threadIdx.x;  // 32 threads
  const float* xr = g_x + (size_t)p * CMID;
  float acc[30];
#pragma unroll
  for (int o = 0; o < 30; o++) acc[o] = 0.f;
  for (int k = lane; k < CMID; k += 32) {
    float xv = xr[k];
    const float* wc = cls_w + (size_t)k * 10;
#pragma unroll
    for (int o = 0; o < 10; o++) acc[o] = fmaf(xv, wc[o], acc[o]);
    const float* wr = reg_w + (size_t)k * 20;
#pragma unroll
    for (int o = 0; o < 20; o++) acc[10 + o] = fmaf(xv, wr[o], acc[10 + o]);
  }
#pragma unroll
  for (int o = 0; o < 30; o++) {
#pragma unroll
    for (int s = 16; s > 0; s >>= 1) acc[o] += __shfl_xor_sync(0xffffffffu, acc[o], s);
  }
  if (lane < NA) {
    const int a = lane;
    float l0 = acc[2 * a + 0] + cls_b[2 * a + 0];
    float l1 = acc[2 * a + 1] + cls_b[2 * a + 1];
    float score = 1.f / (1.f + expf(l0 - l1));  // softmax(...)[1]
    float d0 = acc[10 + 4 * a + 0] + reg_b[4 * a + 0];
    float d1 = acc[10 + 4 * a + 1] + reg_b[4 * a + 1];
    float d2 = acc[10 + 4 * a + 2] + reg_b[4 * a + 2];
    float d3 = acc[10 + 4 * a + 3] + reg_b[4 * a + 3];
    float base = 32.f * (float)(1 << a);  // scales 32,64,128,256,512 ; ratio 1
    float wdt = expf(d2) * base;
    float hgt = expf(d3) * base;
    float xc = (float)(p % WW) + d0;  // FEATURE_STRIDE = 1
    float yc = (float)(p / WW) + d1;
    const int n = p * NA + a;
    g_scores[n] = score;
    float4 b = make_float4(xc - 0.5f * wdt, yc - 0.5f * hgt,
                           xc + 0.5f * wdt, yc + 0.5f * hgt);
    *(float4*)&g_boxes[n * 4] = b;
  }
}

// ---------------- K4: single-block bitonic sort of 8192 64-bit keys ----------------
// key = (~ordered(score) << 32) | idx  => ascending key == (score desc, idx asc),
// exactly matching stable jnp.argsort(-scores).
__global__ __launch_bounds__(1024) void sort_kernel() {
  extern __shared__ unsigned long long skey[];  // 8192 * 8B = 64 KB
  const int t = threadIdx.x;
  for (int i = t; i < 8192; i += 1024) {
    unsigned long long kv;
    if (i < NBOX) {
      unsigned u = __float_as_uint(g_scores[i]);
      unsigned ou = (u & 0x80000000u) ? ~u : (u | 0x80000000u);
      kv = ((unsigned long long)(~ou) << 32) | (unsigned)i;
    } else {
      kv = 0xFFFFFFFFFFFFFFFFull;
    }
    skey[i] = kv;
  }
  __syncthreads();
  for (int k = 2; k <= 8192; k <<= 1) {
    for (int j = k >> 1; j > 0; j >>= 1) {
      for (int i = t; i < 8192; i += 1024) {
        int ixj = i ^ j;
        if (ixj > i) {
          unsigned long long a = skey[i], b = skey[ixj];
          bool up = (i & k) == 0;
          if ((a > b) == up) { skey[i] = b; skey[ixj] = a; }
        }
      }
      __syncthreads();
    }
  }
  for (int i = t; i < NBOX; i += 1024) {
    int idx = (int)(skey[i] & 0xFFFFFFFFull);
    *(float4*)&g_boxsorted[i * 4] = *(const float4*)&g_boxes[idx * 4];
  }
}

// ---------------- K5: greedy NMS, round-per-kept-box ----------------
// Boxes in SMEM (160 KB). Each round: parallel find-next-unsuppressed,
// broadcast, parallel suppression of all later candidates. Chain length =
// number of kept boxes (~100), capped at 300.
__global__ __launch_bounds__(1024) void nms_kernel() {
  extern __shared__ float sb[];  // 5 * 8000 floats
  float* bx1 = sb;
  float* by1 = sb + NBOX;
  float* bx2 = sb + 2 * NBOX;
  float* by2 = sb + 3 * NBOX;
  float* bar = sb + 4 * NBOX;
  __shared__ unsigned long long remv[NWORD];
  __shared__ int ssel[MAXDET];
  __shared__ int s_next;
  const int t = threadIdx.x;
  for (int i = t; i < NBOX; i += 1024) {
    float4 b = *(const float4*)&g_boxsorted[i * 4];
    bx1[i] = b.x; by1[i] = b.y; bx2[i] = b.z; by2[i] = b.w;
    bar[i] = (b.z - b.x) * (b.w - b.y);
  }
  if (t < NWORD) remv[t] = 0ull;
  __syncthreads();

  int count = 0, cur = 0;
  for (;;) {
    if (t == 0) s_next = 0x7FFFFFFF;
    __syncthreads();
    const int wstart = cur >> 6;
    if (t >= wstart && t < NWORD) {
      unsigned long long mw = ~remv[t];
      if (t == wstart) mw &= (~0ull) << (cur & 63);
      if (mw) atomicMin(&s_next, (t << 6) + (__ffsll((long long)mw) - 1));
    }
    __syncthreads();
    const int i = s_next;
    if (i == 0x7FFFFFFF) break;  // no boxes left
    if (t == 0) ssel[count] = i;
    count++;
    const float ix1 = bx1[i], iy1 = by1[i], ix2 = bx2[i], iy2 = by2[i], ia = bar[i];
    for (int j = i + 1 + t; j < NBOX; j += 1024) {
      float iw = fminf(ix2, bx2[j]) - fmaxf(ix1, bx1[j]);
      float ih = fminf(iy2, by2[j]) - fmaxf(iy1, by1[j]);
      iw = fmaxf(iw, 0.f);
      ih = fmaxf(ih, 0.f);
      float inter = iw * ih;
      float iou = inter / (ia + bar[j] - inter);
      if (iou >= 0.7f) atomicOr(&remv[j >> 6], 1ull << (j & 63));
    }
    cur = i + 1;
    if (count >= MAXDET) break;
    __syncthreads();
  }
  __syncthreads();
  for (int r = t; r < MAXDET; r += 1024) {
    float4 v = make_float4(0.f, 0.f, 0.f, 0.f);
    if (r < count) {
      int i = ssel[r];
      v = make_float4(bx1[i], by1[i], bx2[i], by2[i]);
    }
    *(float4*)&g_rois[r * 4] = v;
  }
}

// ---------------- K6: FC head on 300 ROIs + final outputs ----------------
__global__ __launch_bounds__(128) void fc_head_kernel(
    const float* __restrict__ fc1_w, const float* __restrict__ fc1_b,
    const float* __restrict__ clsh_w, const float* __restrict__ clsh_b,
    const float* __restrict__ regh_w, const float* __restrict__ regh_b,
    float* __restrict__ out) {
  const int r = blockIdx.x;
  const int t = threadIdx.x;
  float4 roi = *(const float4*)&g_rois[r * 4];
  float part[8];
#pragma unroll
  for (int o = 0; o < 8; o++) part[o] = 0.f;
  for (int j = t; j < 1024; j += 128) {
    float f = fc1_b[j] + roi.x * fc1_w[j] + roi.y * fc1_w[1024 + j] +
              roi.z * fc1_w[2048 + j] + roi.w * fc1_w[3072 + j];
    f = fmaxf(f, 0.f);
    float4 cw = *(const float4*)&clsh_w[j * 4];
    float4 rw = *(const float4*)&regh_w[j * 4];
    part[0] += f * cw.x; part[1] += f * cw.y; part[2] += f * cw.z; part[3] += f * cw.w;
    part[4] += f * rw.x; part[5] += f * rw.y; part[6] += f * rw.z; part[7] += f * rw.w;
  }
#pragma unroll
  for (int o = 0; o < 8; o++) {
#pragma unroll
    for (int s = 16; s > 0; s >>= 1) part[o] += __shfl_xor_sync(0xffffffffu, part[o], s);
  }
  __shared__ float wred[4][8];
  const int warp = t >> 5, lane = t & 31;
  if (lane == 0) {
#pragma unroll
    for (int o = 0; o < 8; o++) wred[warp][o] = part[o];
  }
  __syncthreads();
  if (t == 0) {
    float v[8];
#pragma unroll
    for (int o = 0; o < 8; o++) v[o] = wred[0][o] + wred[1][o] + wred[2][o] + wred[3][o];
    float l0 = v[0] + clsh_b[0], l1 = v[1] + clsh_b[1];
    float l2 = v[2] + clsh_b[2], l3 = v[3] + clsh_b[3];
    float mx = fmaxf(fmaxf(l0, l1), fmaxf(l2, l3));
    float e0 = expf(l0 - mx), e1 = expf(l1 - mx), e2 = expf(l2 - mx), e3 = expf(l3 - mx);
    float inv = 1.f / (e0 + e1 + e2 + e3);
    out[r * 4 + 0] = e0 * inv;
    out[r * 4 + 1] = e1 * inv;
    out[r * 4 + 2] = e2 * inv;
    out[r * 4 + 3] = e3 * inv;
    out[1200 + r * 4 + 0] = v[4] + regh_b[0];
    out[1200 + r * 4 + 1] = v[5] + regh_b[1];
    out[1200 + r * 4 + 2] = v[6] + regh_b[2];
    out[1200 + r * 4 + 3] = v[7] + regh_b[3];
    *(float4*)&out[2400 + r * 4] = roi;
  }
}

// ---------------- launch ----------------
extern "C" void kernel_launch(void* const* d_in, const int* in_sizes, int n_in,
                              void* d_out, int out_size) {
  const float* feat   = (const float*)d_in[0];
  const float* conv_w = (const float*)d_in[1];
  const float* conv_b = (const float*)d_in[2];
  const float* cls_w  = (const float*)d_in[3];
  const float* cls_b  = (const float*)d_in[4];
  const float* reg_w  = (const float*)d_in[5];
  const float* reg_b  = (const float*)d_in[6];
  const float* fc1_w  = (const float*)d_in[7];
  const float* fc1_b  = (const float*)d_in[8];
  const float* clsh_w = (const float*)d_in[9];
  const float* clsh_b = (const float*)d_in[10];
  const float* regh_w = (const float*)d_in[11];
  const float* regh_b = (const float*)d_in[12];
  float* out = (float*)d_out;

  (void)in_sizes; (void)n_in; (void)out_size;

  cudaFuncSetAttribute(sort_kernel, cudaFuncAttributeMaxDynamicSharedMemorySize, 8192 * 8);
  cudaFuncSetAttribute(nms_kernel, cudaFuncAttributeMaxDynamicSharedMemorySize, NBOX * 5 * 4);

  conv_tap_kernel<<<dim3(25, 4, 9), 256>>>(feat, conv_w);
  reduce_bias_relu<<<1600, 256>>>(conv_b);
  head_conv_kernel<<<1600, 32>>>(cls_w, cls_b, reg_w, reg_b);
  sort_kernel<<<1, 1024, 8192 * 8>>>();
  nms_kernel<<<1, 1024, NBOX * 5 * 4>>>();
  fc_head_kernel<<<300, 128>>>(fc1_w, fc1_b, clsh_w, clsh_b, regh_w, regh_b, out);
}